// round 10
// baseline (speedup 1.0000x reference)
#include <cuda_runtime.h>
#include <math.h>

// Problem constants
#define VOCAB 50000
#define EMB   300
#define HID   256
#define BATCH 128
#define T_H   32
#define T_B   512

// -------- scratch (static device allocations; no cudaMalloc anywhere) --------
__device__ float g_XG_h[(size_t)BATCH * T_H * 768];   // headline x-projections [B*T, 768] (gates 512 | cand 256)
__device__ float g_XG_b[(size_t)BATCH * T_B * 768];   // body x-projections
__device__ float g_out_h[(size_t)BATCH * T_H * HID];  // headline layer-0 outputs
__device__ float g_out_b[(size_t)BATCH * T_B * HID];  // body layer-0 outputs
__device__ float g_hcat [(size_t)BATCH * 512];        // [h_head | h_body] final states

// ---- packed f32x2 helpers (Blackwell FFMA2 path; fp32-exact) ----
__device__ __forceinline__ unsigned long long pack2(float w) {
    unsigned long long r;
    asm("mov.b64 %0, {%1, %1};" : "=l"(r) : "f"(w));
    return r;
}
__device__ __forceinline__ void fma2(unsigned long long& d,
                                     unsigned long long a, unsigned long long b) {
    asm("fma.rn.f32x2 %0, %1, %2, %0;" : "+l"(d) : "l"(a), "l"(b));
}

// ============================================================================
// Generic SGEMM: C[M,N] = A[M,K] @ B[K,N] + bias,  row-major.
// GATHER: A row r = emb[ids[r]] (embedding gather fused into the A-tile load).
// BM=128, BN=64, BK=8, 256 threads, 8x4 micro-tile per thread.
// ============================================================================
template <bool GATHER>
__global__ __launch_bounds__(256)
void sgemm_kernel(const float* __restrict__ A, const int* __restrict__ ids, int lda,
                  const float* __restrict__ Bm, int ldb,
                  const float* __restrict__ bias,
                  float* __restrict__ C, int ldc, int coff,
                  int M, int N, int K)
{
    const int BM = 128, BN = 64, BK = 8;
    __shared__ float As[BK][BM];
    __shared__ float Bs[BK][BN];

    int nbn = N / BN;
    int bm = blockIdx.x / nbn;
    int bn = blockIdx.x % nbn;
    int tid = threadIdx.x;
    int tx = tid & 15;        // 0..15 -> 4 cols each
    int ty = tid >> 4;        // 0..15 -> 8 rows each

    float acc[8][4];
#pragma unroll
    for (int i = 0; i < 8; i++)
#pragma unroll
        for (int j = 0; j < 4; j++) acc[i][j] = 0.0f;

    // A-tile loader mapping: thread -> (row ar, 4 consecutive k at ak)
    int ar = tid >> 1;            // 0..127
    int ak = (tid & 1) * 4;       // 0 or 4
    int arow = bm * BM + ar;
    const float* arow_ptr;
    if (GATHER) arow_ptr = A + (size_t)ids[arow] * lda;
    else        arow_ptr = A + (size_t)arow * lda;

    // B-tile loader mapping: thread -> (k-row bk, 2 consecutive cols bc)
    int bkr = tid >> 5;           // 0..7
    int bc  = (tid & 31) * 2;     // 0..62
    const float* bptr = Bm + (size_t)bn * BN + bc;

    for (int k0 = 0; k0 < K; k0 += BK) {
        float4 av = make_float4(0.f, 0.f, 0.f, 0.f);
        if (k0 + ak < K) av = *(const float4*)(arow_ptr + k0 + ak);
        float2 bv = make_float2(0.f, 0.f);
        if (k0 + bkr < K) bv = *(const float2*)(bptr + (size_t)(k0 + bkr) * ldb);

        __syncthreads();
        As[ak + 0][ar] = av.x; As[ak + 1][ar] = av.y;
        As[ak + 2][ar] = av.z; As[ak + 3][ar] = av.w;
        Bs[bkr][bc] = bv.x; Bs[bkr][bc + 1] = bv.y;
        __syncthreads();

#pragma unroll
        for (int kk = 0; kk < BK; kk++) {
            float4 b4 = *(const float4*)&Bs[kk][tx * 4];
            float4 a0 = *(const float4*)&As[kk][ty * 8];
            float4 a1 = *(const float4*)&As[kk][ty * 8 + 4];
            float arr[8] = {a0.x, a0.y, a0.z, a0.w, a1.x, a1.y, a1.z, a1.w};
            float brr[4] = {b4.x, b4.y, b4.z, b4.w};
#pragma unroll
            for (int i = 0; i < 8; i++)
#pragma unroll
                for (int j = 0; j < 4; j++)
                    acc[i][j] += arr[i] * brr[j];
        }
    }

    float4 bb = *(const float4*)&bias[bn * BN + tx * 4];
    float bbr[4] = {bb.x, bb.y, bb.z, bb.w};
#pragma unroll
    for (int i = 0; i < 8; i++) {
        int row = bm * BM + ty * 8 + i;
        float4 o;
        o.x = acc[i][0] + bbr[0];
        o.y = acc[i][1] + bbr[1];
        o.z = acc[i][2] + bbr[2];
        o.w = acc[i][3] + bbr[3];
        *(float4*)(C + (size_t)row * ldc + coff + bn * BN + tx * 4) = o;
    }
}

// ============================================================================
// GRU recurrent scan, round 9: 4-way k-split + float4 weight loads + FFMA2.
// One block = 2 batch rows, 512 threads (16 warps):
//   k-quarter q = tid>>7 in {0..3} accumulates k in [64q, 64q+64)
//   gate phase: thread owns 4 gate columns  (LDG.128 per k-iter)
//   cand phase: thread owns 2 cand columns  (LDG.64  per k-iter)
// The two batch rows are packed as f32x2 so each MAC is one fma.rn.f32x2.
// Partials are combined via smem once per phase.
// Grid = 128 blocks: [0,64) = body stream, [64,128) = headline stream.
// ============================================================================
struct ScanArgs {
    const float* XG;    // [B*T, 768] x-projections (gates 0..511, cand 512..767)
    const float* Wgh;   // [256, 512] h-part of gate weights (k-major)
    const float* Wch;   // [256, 256] h-part of cand weights (k-major)
    const int*   ids;   // [B, T]
    float*       outs;  // [B*T, 256] or nullptr
    float*       hfin;  // g_hcat or nullptr
    int          hoff;  // column offset into g_hcat
    int          T;
};

__global__ __launch_bounds__(512)
void gru_scan_kernel(ScanArgs body, ScanArgs head)
{
    ScanArgs A = (blockIdx.x < 64) ? body : head;
    int bid = blockIdx.x & 63;
    int b0 = bid * 2;
    int b1 = b0 + 1;
    int tid = threadIdx.x;
    int q  = tid >> 7;            // k-quarter 0..3 (uniform per warp)
    int qt = tid & 127;           // thread-in-quarter
    int kq = q * 64;              // k range start

    __shared__ float2 sh_h2 [HID];          // (h_b0[k], h_b1[k])
    __shared__ float2 sh_rh2[HID];          // (r*h pairs)
    __shared__ float2 sh_u2 [HID];          // update-gate pairs
    __shared__ float2 sh_part [4][2 * HID]; // gate partials [quarter][col]   16KB
    __shared__ float2 sh_cpart[4][HID];     // cand partials [quarter][col]    8KB

    if (tid < HID) sh_h2[tid] = make_float2(0.f, 0.f);
    __syncthreads();

    const int T = A.T;
    const int c4 = qt * 4;        // gate columns owned
    const int c2 = qt * 2;        // cand columns owned

    const float* __restrict__ wg_base = A.Wgh + (size_t)kq * 512 + c4;
    const float* __restrict__ wc_base = A.Wch + (size_t)kq * 256 + c2;

    const unsigned long long* sh_h2u  = (const unsigned long long*)sh_h2;
    const unsigned long long* sh_rh2u = (const unsigned long long*)sh_rh2;

    for (int t = 0; t < T; t++) {
        const float* xg0 = A.XG + ((size_t)(b0 * T + t)) * 768;
        const float* xg1 = A.XG + ((size_t)(b1 * T + t)) * 768;

        // --- prefetch this step's x-parts + validity (hide DRAM latency) ---
        float xv0 = xg0[tid];              // gate x-part, col = tid (0..511)
        float xv1 = xg1[tid];
        float xc0 = 0.f, xc1 = 0.f;
        if (tid < HID) {
            xc0 = xg0[512 + tid];          // cand x-part
            xc1 = xg1[512 + tid];
        }
        bool v0 = (A.ids[b0 * T + t] != 0);
        bool v1 = (A.ids[b1 * T + t] != 0);

        // --- phase 1: gate partials, k in [kq,kq+64), cols c4..c4+3 ---
        {
            unsigned long long acc0 = 0ull, acc1 = 0ull, acc2 = 0ull, acc3 = 0ull;
#pragma unroll 16
            for (int kk = 0; kk < 64; kk++) {
                float4 w = *(const float4*)(wg_base + (size_t)kk * 512);
                unsigned long long h2 = sh_h2u[kq + kk];
                fma2(acc0, pack2(w.x), h2);
                fma2(acc1, pack2(w.y), h2);
                fma2(acc2, pack2(w.z), h2);
                fma2(acc3, pack2(w.w), h2);
            }
            unsigned long long* dst = (unsigned long long*)&sh_part[q][c4];
            dst[0] = acc0; dst[1] = acc1; dst[2] = acc2; dst[3] = acc3;
        }
        __syncthreads();

        // --- phase 2: combine quarters + sigmoid; col c = tid (512 cols) ---
        {
            int c = tid;
            float2 p0 = sh_part[0][c];
            float2 p1 = sh_part[1][c];
            float2 p2 = sh_part[2][c];
            float2 p3 = sh_part[3][c];
            float s0 = (p0.x + p1.x) + (p2.x + p3.x) + xv0;
            float s1 = (p0.y + p1.y) + (p2.y + p3.y) + xv1;
            float g0 = 1.f / (1.f + expf(-s0));
            float g1 = 1.f / (1.f + expf(-s1));
            if (c < HID) {                 // r gate -> r*h
                float2 h2 = sh_h2[c];
                sh_rh2[c] = make_float2(g0 * h2.x, g1 * h2.y);
            } else {                       // u gate
                sh_u2[c - HID] = make_float2(g0, g1);
            }
        }
        __syncthreads();

        // --- phase 3: cand partials, k in [kq,kq+64), cols c2..c2+1 ---
        {
            unsigned long long cacc0 = 0ull, cacc1 = 0ull;
#pragma unroll 16
            for (int kk = 0; kk < 64; kk++) {
                float2 w = *(const float2*)(wc_base + (size_t)kk * 256);
                unsigned long long rh = sh_rh2u[kq + kk];
                fma2(cacc0, pack2(w.x), rh);
                fma2(cacc1, pack2(w.y), rh);
            }
            unsigned long long* dst = (unsigned long long*)&sh_cpart[q][c2];
            dst[0] = cacc0; dst[1] = cacc1;
        }
        __syncthreads();

        // --- phase 4: combine + tanh + state update (threads < 256) ---
        if (tid < HID) {
            int c = tid;
            float2 p0 = sh_cpart[0][c];
            float2 p1 = sh_cpart[1][c];
            float2 p2 = sh_cpart[2][c];
            float2 p3 = sh_cpart[3][c];
            float cc0 = tanhf((p0.x + p1.x) + (p2.x + p3.x) + xc0);
            float cc1 = tanhf((p0.y + p1.y) + (p2.y + p3.y) + xc1);
            float2 u2 = sh_u2[c];
            float2 ho = sh_h2[c];
            float hn0 = u2.x * ho.x + (1.f - u2.x) * cc0;
            float hn1 = u2.y * ho.y + (1.f - u2.y) * cc1;
            if (A.outs) {
                A.outs[((size_t)(b0 * T + t)) * 256 + c] = v0 ? hn0 : 0.f;
                A.outs[((size_t)(b1 * T + t)) * 256 + c] = v1 ? hn1 : 0.f;
            }
            sh_h2[c] = make_float2(v0 ? hn0 : ho.x, v1 ? hn1 : ho.y);
        }
        __syncthreads();
    }

    if (A.hfin && tid < HID) {
        float2 h2 = sh_h2[tid];
        A.hfin[(size_t)b0 * 512 + A.hoff + tid] = h2.x;
        A.hfin[(size_t)b1 * 512 + A.hoff + tid] = h2.y;
    }
}

// ============================================================================
// Final projection: out[128,4] = [h_head | h_body] @ W_pred + b_pred
// ============================================================================
__global__ void final_pred_kernel(const float* __restrict__ Wp,
                                  const float* __restrict__ bp,
                                  float* __restrict__ out)
{
    int b = threadIdx.x;   // 0..127
    float a0 = bp[0], a1 = bp[1], a2 = bp[2], a3 = bp[3];
    const float* h = g_hcat + (size_t)b * 512;
#pragma unroll 8
    for (int j = 0; j < 512; j++) {
        float hv = h[j];
        float4 w = *(const float4*)(Wp + j * 4);
        a0 += hv * w.x; a1 += hv * w.y; a2 += hv * w.z; a3 += hv * w.w;
    }
    *(float4*)(out + b * 4) = make_float4(a0, a1, a2, a3);
}

// ============================================================================
// Launch: L0 x-GEMMs -> L0 scan -> L1 x-GEMMs -> L1 scan -> final projection
// ============================================================================
extern "C" void kernel_launch(void* const* d_in, const int* in_sizes, int n_in,
                              void* d_out, int out_size)
{
    (void)n_in; (void)out_size;

    // Fixed slots (same in both plausible metadata orders)
    const int*   ids_h  = (const int*)d_in[0];
    const int*   ids_b  = (const int*)d_in[1];
    const float* emb    = (const float*)d_in[2];

    // Detect metadata layout from element counts.
    const float *hd0_Wg, *hd0_bg, *hd0_Wc, *hd0_bc;
    const float *hd1_Wg, *hd1_bg, *hd1_Wc, *hd1_bc;
    const float *bd0_Wg, *bd0_bg, *bd0_Wc, *bd0_bc;
    const float *bd1_Wg, *bd1_bg, *bd1_Wc, *bd1_bc;
    const float *W_pred, *b_pred;

    if (in_sizes[3] == (2 * HID) * 4 && in_sizes[4] == 4) {
        // dict order
        W_pred = (const float*)d_in[3];
        b_pred = (const float*)d_in[4];
        hd0_Wg = (const float*)d_in[5];  hd0_bg = (const float*)d_in[6];
        hd0_Wc = (const float*)d_in[7];  hd0_bc = (const float*)d_in[8];
        hd1_Wg = (const float*)d_in[9];  hd1_bg = (const float*)d_in[10];
        hd1_Wc = (const float*)d_in[11]; hd1_bc = (const float*)d_in[12];
        bd0_Wg = (const float*)d_in[13]; bd0_bg = (const float*)d_in[14];
        bd0_Wc = (const float*)d_in[15]; bd0_bc = (const float*)d_in[16];
        bd1_Wg = (const float*)d_in[17]; bd1_bg = (const float*)d_in[18];
        bd1_Wc = (const float*)d_in[19]; bd1_bc = (const float*)d_in[20];
    } else {
        // signature order
        hd0_Wg = (const float*)d_in[3];  hd0_bg = (const float*)d_in[4];
        hd0_Wc = (const float*)d_in[5];  hd0_bc = (const float*)d_in[6];
        hd1_Wg = (const float*)d_in[7];  hd1_bg = (const float*)d_in[8];
        hd1_Wc = (const float*)d_in[9];  hd1_bc = (const float*)d_in[10];
        bd0_Wg = (const float*)d_in[11]; bd0_bg = (const float*)d_in[12];
        bd0_Wc = (const float*)d_in[13]; bd0_bc = (const float*)d_in[14];
        bd1_Wg = (const float*)d_in[15]; bd1_bg = (const float*)d_in[16];
        bd1_Wc = (const float*)d_in[17]; bd1_bc = (const float*)d_in[18];
        W_pred = (const float*)d_in[19];
        b_pred = (const float*)d_in[20];
    }

    float* out = (float*)d_out;

    float *XG_h, *XG_b, *out_h, *out_b, *hcat;
    cudaGetSymbolAddress((void**)&XG_h, g_XG_h);
    cudaGetSymbolAddress((void**)&XG_b, g_XG_b);
    cudaGetSymbolAddress((void**)&out_h, g_out_h);
    cudaGetSymbolAddress((void**)&out_b, g_out_b);
    cudaGetSymbolAddress((void**)&hcat, g_hcat);

    const int Mh = BATCH * T_H;   // 4096
    const int Mb = BATCH * T_B;   // 65536

    // ---- Layer-0 x-projections (embedding gather fused) ----
    sgemm_kernel<true><<<(Mh / 128) * (512 / 64), 256>>>(
        emb, ids_h, EMB, hd0_Wg, 512, hd0_bg, XG_h, 768, 0,   Mh, 512, EMB);
    sgemm_kernel<true><<<(Mh / 128) * (256 / 64), 256>>>(
        emb, ids_h, EMB, hd0_Wc, 256, hd0_bc, XG_h, 768, 512, Mh, 256, EMB);
    sgemm_kernel<true><<<(Mb / 128) * (512 / 64), 256>>>(
        emb, ids_b, EMB, bd0_Wg, 512, bd0_bg, XG_b, 768, 0,   Mb, 512, EMB);
    sgemm_kernel<true><<<(Mb / 128) * (256 / 64), 256>>>(
        emb, ids_b, EMB, bd0_Wc, 256, bd0_bc, XG_b, 768, 512, Mb, 256, EMB);

    // ---- Layer-0 scan (body + headline in one launch) ----
    {
        ScanArgs body = { XG_b, bd0_Wg + (size_t)EMB * 512, bd0_Wc + (size_t)EMB * 256,
                          ids_b, out_b, nullptr, 0, T_B };
        ScanArgs head = { XG_h, hd0_Wg + (size_t)EMB * 512, hd0_Wc + (size_t)EMB * 256,
                          ids_h, out_h, nullptr, 0, T_H };
        gru_scan_kernel<<<128, 512>>>(body, head);
    }

    // ---- Layer-1 x-projections (reuse XG buffers) ----
    sgemm_kernel<false><<<(Mh / 128) * (512 / 64), 256>>>(
        out_h, nullptr, HID, hd1_Wg, 512, hd1_bg, XG_h, 768, 0,   Mh, 512, HID);
    sgemm_kernel<false><<<(Mh / 128) * (256 / 64), 256>>>(
        out_h, nullptr, HID, hd1_Wc, 256, hd1_bc, XG_h, 768, 512, Mh, 256, HID);
    sgemm_kernel<false><<<(Mb / 128) * (512 / 64), 256>>>(
        out_b, nullptr, HID, bd1_Wg, 512, bd1_bg, XG_b, 768, 0,   Mb, 512, HID);
    sgemm_kernel<false><<<(Mb / 128) * (256 / 64), 256>>>(
        out_b, nullptr, HID, bd1_Wc, 256, bd1_bc, XG_b, 768, 512, Mb, 256, HID);

    // ---- Layer-1 scan -> final hidden states ----
    {
        ScanArgs body = { XG_b, bd1_Wg + (size_t)HID * 512, bd1_Wc + (size_t)HID * 256,
                          ids_b, nullptr, hcat, 256, T_B };
        ScanArgs head = { XG_h, hd1_Wg + (size_t)HID * 512, hd1_Wc + (size_t)HID * 256,
                          ids_h, nullptr, hcat, 0, T_H };
        gru_scan_kernel<<<128, 512>>>(body, head);
    }

    // ---- Final projection ----
    final_pred_kernel<<<1, 128>>>(W_pred, b_pred, out);
}

// round 11
// speedup vs baseline: 1.1156x; 1.1156x over previous
#include <cuda_runtime.h>
#include <math.h>

// Problem constants
#define VOCAB 50000
#define EMB   300
#define HID   256
#define BATCH 128
#define T_H   32
#define T_B   512

typedef unsigned long long ULL;

// -------- scratch (static device allocations; no cudaMalloc anywhere) --------
__device__ float g_XG_h[(size_t)BATCH * T_H * 768];   // headline x-projections [B*T, 768]
__device__ float g_XG_b[(size_t)BATCH * T_B * 768];   // body x-projections
__device__ float g_out_h[(size_t)BATCH * T_H * HID];  // headline layer-0 outputs
__device__ float g_out_b[(size_t)BATCH * T_B * HID];  // body layer-0 outputs
__device__ float g_hcat [(size_t)BATCH * 512];        // [h_head | h_body] final states

// -------- pair-block mailboxes (double-buffered) + flags --------
__device__ ULL   g_mb_rh[2][64][256][4];   // rh, duplicated pairs, [buf][pg][col][row]
__device__ float g_mb_u [2][64][4][256];   // u gates            [buf][pg][row][col]
__device__ float g_mb_c [2][64][4][256];   // candidate          [buf][pg][row][col]
__device__ unsigned g_f_rh[64];            // role A: rh published   (value = t+1)
__device__ unsigned g_f_ac[64];            // role A: c[0:128) published
__device__ unsigned g_f_bc[64];            // role B: u + c[128:256) published

__global__ void reset_flags_kernel() {
    int t = threadIdx.x;
    if (t < 64) { g_f_rh[t] = 0; g_f_ac[t] = 0; g_f_bc[t] = 0; }
}

// ---- packed f32x2 helpers (fp32-exact) ----
__device__ __forceinline__ void fma2(ULL& d, ULL a, ULL b) {
    asm("fma.rn.f32x2 %0, %1, %2, %0;" : "+l"(d) : "l"(a), "l"(b));
}
__device__ __forceinline__ ULL add2(ULL a, ULL b) {
    ULL d; asm("add.rn.f32x2 %0, %1, %2;" : "=l"(d) : "l"(a), "l"(b)); return d;
}
__device__ __forceinline__ ULL dup2(float x) {
    ULL r; asm("mov.b64 %0, {%1, %1};" : "=l"(r) : "f"(x)); return r;
}
__device__ __forceinline__ float2 u2f(ULL v) {
    float2 f; asm("mov.b64 {%0, %1}, %2;" : "=f"(f.x), "=f"(f.y) : "l"(v)); return f;
}

// ---- scoped sync helpers ----
__device__ __forceinline__ void st_rel(unsigned* p, unsigned v) {
    asm volatile("st.release.gpu.global.u32 [%0], %1;" :: "l"(p), "r"(v) : "memory");
}
__device__ __forceinline__ unsigned ld_acq(const unsigned* p) {
    unsigned v;
    asm volatile("ld.acquire.gpu.global.u32 %0, [%1];" : "=r"(v) : "l"(p) : "memory");
    return v;
}
__device__ __forceinline__ float ldcg_f(const float* p) {
    float v; asm volatile("ld.global.cg.f32 %0, [%1];" : "=f"(v) : "l"(p)); return v;
}
__device__ __forceinline__ ULL ldcg_u64(const ULL* p) {
    ULL v; asm volatile("ld.global.cg.u64 %0, [%1];" : "=l"(v) : "l"(p)); return v;
}
__device__ __forceinline__ void waitflag(unsigned* p, unsigned want) {
    while (ld_acq(p) < want) __nanosleep(40);
}

// ============================================================================
// Generic SGEMM (unchanged): C[M,N] = A[M,K] @ B[K,N] + bias, row-major.
// ============================================================================
template <bool GATHER>
__global__ __launch_bounds__(256)
void sgemm_kernel(const float* __restrict__ A, const int* __restrict__ ids, int lda,
                  const float* __restrict__ Bm, int ldb,
                  const float* __restrict__ bias,
                  float* __restrict__ C, int ldc, int coff,
                  int M, int N, int K)
{
    const int BM = 128, BN = 64, BK = 8;
    __shared__ float As[BK][BM];
    __shared__ float Bs[BK][BN];

    int nbn = N / BN;
    int bm = blockIdx.x / nbn;
    int bn = blockIdx.x % nbn;
    int tid = threadIdx.x;
    int tx = tid & 15;
    int ty = tid >> 4;

    float acc[8][4];
#pragma unroll
    for (int i = 0; i < 8; i++)
#pragma unroll
        for (int j = 0; j < 4; j++) acc[i][j] = 0.0f;

    int ar = tid >> 1;
    int ak = (tid & 1) * 4;
    int arow = bm * BM + ar;
    const float* arow_ptr;
    if (GATHER) arow_ptr = A + (size_t)ids[arow] * lda;
    else        arow_ptr = A + (size_t)arow * lda;

    int bkr = tid >> 5;
    int bc  = (tid & 31) * 2;
    const float* bptr = Bm + (size_t)bn * BN + bc;

    for (int k0 = 0; k0 < K; k0 += BK) {
        float4 av = make_float4(0.f, 0.f, 0.f, 0.f);
        if (k0 + ak < K) av = *(const float4*)(arow_ptr + k0 + ak);
        float2 bv = make_float2(0.f, 0.f);
        if (k0 + bkr < K) bv = *(const float2*)(bptr + (size_t)(k0 + bkr) * ldb);

        __syncthreads();
        As[ak + 0][ar] = av.x; As[ak + 1][ar] = av.y;
        As[ak + 2][ar] = av.z; As[ak + 3][ar] = av.w;
        Bs[bkr][bc] = bv.x; Bs[bkr][bc + 1] = bv.y;
        __syncthreads();

#pragma unroll
        for (int kk = 0; kk < BK; kk++) {
            float4 b4 = *(const float4*)&Bs[kk][tx * 4];
            float4 a0 = *(const float4*)&As[kk][ty * 8];
            float4 a1 = *(const float4*)&As[kk][ty * 8 + 4];
            float arr[8] = {a0.x, a0.y, a0.z, a0.w, a1.x, a1.y, a1.z, a1.w};
            float brr[4] = {b4.x, b4.y, b4.z, b4.w};
#pragma unroll
            for (int i = 0; i < 8; i++)
#pragma unroll
                for (int j = 0; j < 4; j++)
                    acc[i][j] += arr[i] * brr[j];
        }
    }

    float4 bb = *(const float4*)&bias[bn * BN + tx * 4];
    float bbr[4] = {bb.x, bb.y, bb.z, bb.w};
#pragma unroll
    for (int i = 0; i < 8; i++) {
        int row = bm * BM + ty * 8 + i;
        float4 o;
        o.x = acc[i][0] + bbr[0];
        o.y = acc[i][1] + bbr[1];
        o.z = acc[i][2] + bbr[2];
        o.w = acc[i][3] + bbr[3];
        *(float4*)(C + (size_t)row * ldc + coff + bn * BN + tx * 4) = o;
    }
}

// ============================================================================
// GRU scan, round 11: cooperative pair-blocks.
// A group = 4 batch rows handled by TWO blocks:
//   role 0 (A): r-gate cols [0,256)   + cand cols [0,128)
//   role 1 (B): u-gate cols [256,512) + cand cols [128,256)
// Each block streams only 384 KB of weights per step. Per-step vectors
// (rh / u / c) are exchanged through L2 mailboxes with release/acquire flags.
// Grid = 128 blocks (all co-resident): [0,64) body, [64,128) head.
// ============================================================================
struct ScanArgs {
    const float* XG;
    const float* Wgh;   // [256,512] k-major h-part of gate weights
    const float* Wch;   // [256,256] k-major h-part of cand weights
    const int*   ids;
    float*       outs;
    float*       hfin;
    int          hoff;
    int          T;
};

__global__ __launch_bounds__(512)
void gru_scan_pair_kernel(ScanArgs body, ScanArgs head)
{
    const int bx = blockIdx.x;
    const int stream = bx >> 6;
    ScanArgs A = stream ? head : body;
    const int within = bx & 63;
    const int pgl  = within >> 1;       // pair-group within stream (0..31)
    const int role = within & 1;        // 0 = A, 1 = B
    const int pg   = stream * 32 + pgl; // global mailbox index
    const int b0   = pgl * 4;           // first batch row of group
    const int tid  = threadIdx.x;
    const int T    = A.T;

    // ---- shared memory (44 KB) ----
    __shared__ ULL   sh_part[2048];     // gate view [4][128][4] / cand view [8][64][4]
    __shared__ ULL   h_dup [256][4];    // h duplicated: (h,h) per (col,row)
    __shared__ ULL   rh_dup[256][4];    // r*h duplicated
    __shared__ float h_s[4][256];       // h scalar
    __shared__ float u_s[4][256];       // u gates (role B fills own; role A loads mb)
    __shared__ float c_s[4][256];       // candidate (own half at cand-combine)
    __shared__ int   sv[4];             // validity ids for this step

    // init h = 0
    for (int i = tid; i < 1024; i += 512) {
        ((ULL*)h_dup)[i] = 0ull;
        ((float*)h_s)[i] = 0.f;
    }
    __syncthreads();

    const int colbase_g = role * 256;   // gate column base (global)
    const int candbase  = role * 128;   // cand column base

    // gate mainloop mapping: 128 col-owners (2 cols each) x 4 k-splits (64 k)
    const int og  = tid & 127;
    const int ksg = tid >> 7;
    const int kqg = ksg * 64;
    const float* wg = A.Wgh + (size_t)kqg * 512 + colbase_g + og * 2;

    // cand mainloop mapping: 64 col-owners (2 cols each) x 8 k-splits (32 k)
    const int oc  = tid & 63;
    const int ksc = tid >> 6;
    const int kqc = ksc * 32;
    const float* wc = A.Wch + (size_t)kqc * 256 + candbase + oc * 2;

    // gate combine mapping: 128 col-pairs x 4 rows
    const int cpg = tid >> 2;
    const int rg  = tid & 3;
    const int gcl = cpg * 2;            // local gate col (== h col for role A)

    // cand combine mapping (tid < 256): 64 col-pairs x 4 rows
    const int cpc = (tid & 255) >> 2;
    const int rc  = tid & 3;
    const int ccl = cpc * 2;

    for (int t = 0; t < T; t++) {
        const int buf = t & 1;

        // ---- prefetch x-parts + validity ----
        const float2 xg2 = *(const float2*)(A.XG +
            (size_t)((b0 + rg) * T + t) * 768 + colbase_g + gcl);
        float2 xc2 = make_float2(0.f, 0.f);
        if (tid < 256)
            xc2 = *(const float2*)(A.XG +
                (size_t)((b0 + rc) * T + t) * 768 + 512 + candbase + ccl);
        if (tid < 4) sv[tid] = A.ids[(b0 + tid) * T + t];

        // ---- gate partials: 2 cols x 4 rows over 64 k ----
        {
            ULL a0 = 0ull, a1 = 0ull, a2 = 0ull, a3 = 0ull;
#pragma unroll 16
            for (int kk = 0; kk < 64; kk++) {
                ULL w2 = *(const ULL*)(wg + (size_t)kk * 512);
                const ULL* hp = h_dup[kqg + kk];
                fma2(a0, w2, hp[0]);
                fma2(a1, w2, hp[1]);
                fma2(a2, w2, hp[2]);
                fma2(a3, w2, hp[3]);
            }
            ULL* dst = &sh_part[(size_t)(ksg * 128 + og) * 4];
            dst[0] = a0; dst[1] = a1; dst[2] = a2; dst[3] = a3;
        }
        __syncthreads();

        // ---- gate combine + sigmoid; write rh (A) or u (B) ----
        {
            int base = cpg * 4 + rg;
            ULL s = add2(add2(sh_part[base], sh_part[base + 512]),
                         add2(sh_part[base + 1024], sh_part[base + 1536]));
            float2 sf = u2f(s);
            float g0 = 1.f / (1.f + expf(-(sf.x + xg2.x)));
            float g1 = 1.f / (1.f + expf(-(sf.y + xg2.y)));
            if (role == 0) {
                float rh0 = g0 * h_s[rg][gcl];
                float rh1 = g1 * h_s[rg][gcl + 1];
                ULL d0 = dup2(rh0), d1 = dup2(rh1);
                rh_dup[gcl][rg]     = d0;
                rh_dup[gcl + 1][rg] = d1;
                g_mb_rh[buf][pg][gcl][rg]     = d0;
                g_mb_rh[buf][pg][gcl + 1][rg] = d1;
            } else {
                u_s[rg][gcl]     = g0;
                u_s[rg][gcl + 1] = g1;
                *(float2*)&g_mb_u[buf][pg][rg][gcl] = make_float2(g0, g1);
            }
        }
        __syncthreads();   // rh_dup/u_s complete; mailbox writes issued

        if (role == 0) {
            if (tid == 0) st_rel(&g_f_rh[pg], (unsigned)(t + 1));
        } else {
            if (tid == 0) waitflag(&g_f_rh[pg], (unsigned)(t + 1));
            __syncthreads();
            // load partner's rh into rh_dup (L2 reads, bypass L1)
            const ULL* src = &g_mb_rh[buf][pg][0][0];
            ULL* dst = &rh_dup[0][0];
            dst[tid]       = ldcg_u64(src + tid);
            dst[tid + 512] = ldcg_u64(src + tid + 512);
            __syncthreads();
        }

        // ---- cand partials: 2 cols x 4 rows over 32 k ----
        {
            ULL a0 = 0ull, a1 = 0ull, a2 = 0ull, a3 = 0ull;
#pragma unroll 16
            for (int kk = 0; kk < 32; kk++) {
                ULL w2 = *(const ULL*)(wc + (size_t)kk * 256);
                const ULL* rp = rh_dup[kqc + kk];
                fma2(a0, w2, rp[0]);
                fma2(a1, w2, rp[1]);
                fma2(a2, w2, rp[2]);
                fma2(a3, w2, rp[3]);
            }
            ULL* dst = &sh_part[(size_t)(ksc * 64 + oc) * 4];
            dst[0] = a0; dst[1] = a1; dst[2] = a2; dst[3] = a3;
        }
        __syncthreads();

        // ---- cand combine + tanh (tid < 256) ----
        if (tid < 256) {
            int base = cpc * 4 + rc;
            ULL s = add2(add2(add2(sh_part[base],        sh_part[base + 256]),
                              add2(sh_part[base + 512],  sh_part[base + 768])),
                         add2(add2(sh_part[base + 1024], sh_part[base + 1280]),
                              add2(sh_part[base + 1536], sh_part[base + 1792])));
            float2 sf = u2f(s);
            float c0 = tanhf(sf.x + xc2.x);
            float c1 = tanhf(sf.y + xc2.y);
            int gcol = candbase + ccl;
            c_s[rc][gcol]     = c0;
            c_s[rc][gcol + 1] = c1;
            *(float2*)&g_mb_c[buf][pg][rc][gcol] = make_float2(c0, c1);
        }
        __syncthreads();   // mailbox c writes issued

        if (tid == 0) {
            if (role == 0) { st_rel(&g_f_ac[pg], (unsigned)(t + 1));
                             waitflag(&g_f_bc[pg], (unsigned)(t + 1)); }
            else           { st_rel(&g_f_bc[pg], (unsigned)(t + 1));
                             waitflag(&g_f_ac[pg], (unsigned)(t + 1)); }
        }
        __syncthreads();

        // ---- update: h_new = u*h + (1-u)*c, both roles compute full h ----
        {
#pragma unroll
            for (int p = 0; p < 2; p++) {
                int r   = p * 2 + (tid >> 8);
                int col = tid & 255;
                float u = (role == 0) ? ldcg_f(&g_mb_u[buf][pg][r][col])
                                      : u_s[r][col];
                bool own = (role == 0) ? (col < 128) : (col >= 128);
                float c = own ? c_s[r][col] : ldcg_f(&g_mb_c[buf][pg][r][col]);
                float ho = h_s[r][col];
                float hn = u * ho + (1.f - u) * c;
                bool v = (sv[r] != 0);
                float hkeep = v ? hn : ho;
                if (A.outs && own)
                    A.outs[(size_t)((b0 + r) * T + t) * 256 + col] = v ? hn : 0.f;
                h_s[r][col]   = hkeep;
                h_dup[col][r] = dup2(hkeep);
            }
        }
        __syncthreads();   // h ready for next step
    }

    // ---- final hidden state ----
    if (A.hfin) {
#pragma unroll
        for (int p = 0; p < 2; p++) {
            int r   = p * 2 + (tid >> 8);
            int col = tid & 255;
            bool own = (role == 0) ? (col < 128) : (col >= 128);
            if (own)
                A.hfin[(size_t)(b0 + r) * 512 + A.hoff + col] = h_s[r][col];
        }
    }
}

// ============================================================================
// Final projection: out[128,4] = [h_head | h_body] @ W_pred + b_pred
// ============================================================================
__global__ void final_pred_kernel(const float* __restrict__ Wp,
                                  const float* __restrict__ bp,
                                  float* __restrict__ out)
{
    int b = threadIdx.x;
    float a0 = bp[0], a1 = bp[1], a2 = bp[2], a3 = bp[3];
    const float* h = g_hcat + (size_t)b * 512;
#pragma unroll 8
    for (int j = 0; j < 512; j++) {
        float hv = h[j];
        float4 w = *(const float4*)(Wp + j * 4);
        a0 += hv * w.x; a1 += hv * w.y; a2 += hv * w.z; a3 += hv * w.w;
    }
    *(float4*)(out + b * 4) = make_float4(a0, a1, a2, a3);
}

// ============================================================================
// Launch
// ============================================================================
extern "C" void kernel_launch(void* const* d_in, const int* in_sizes, int n_in,
                              void* d_out, int out_size)
{
    (void)n_in; (void)out_size;

    const int*   ids_h  = (const int*)d_in[0];
    const int*   ids_b  = (const int*)d_in[1];
    const float* emb    = (const float*)d_in[2];

    const float *hd0_Wg, *hd0_bg, *hd0_Wc, *hd0_bc;
    const float *hd1_Wg, *hd1_bg, *hd1_Wc, *hd1_bc;
    const float *bd0_Wg, *bd0_bg, *bd0_Wc, *bd0_bc;
    const float *bd1_Wg, *bd1_bg, *bd1_Wc, *bd1_bc;
    const float *W_pred, *b_pred;

    if (in_sizes[3] == (2 * HID) * 4 && in_sizes[4] == 4) {
        W_pred = (const float*)d_in[3];
        b_pred = (const float*)d_in[4];
        hd0_Wg = (const float*)d_in[5];  hd0_bg = (const float*)d_in[6];
        hd0_Wc = (const float*)d_in[7];  hd0_bc = (const float*)d_in[8];
        hd1_Wg = (const float*)d_in[9];  hd1_bg = (const float*)d_in[10];
        hd1_Wc = (const float*)d_in[11]; hd1_bc = (const float*)d_in[12];
        bd0_Wg = (const float*)d_in[13]; bd0_bg = (const float*)d_in[14];
        bd0_Wc = (const float*)d_in[15]; bd0_bc = (const float*)d_in[16];
        bd1_Wg = (const float*)d_in[17]; bd1_bg = (const float*)d_in[18];
        bd1_Wc = (const float*)d_in[19]; bd1_bc = (const float*)d_in[20];
    } else {
        hd0_Wg = (const float*)d_in[3];  hd0_bg = (const float*)d_in[4];
        hd0_Wc = (const float*)d_in[5];  hd0_bc = (const float*)d_in[6];
        hd1_Wg = (const float*)d_in[7];  hd1_bg = (const float*)d_in[8];
        hd1_Wc = (const float*)d_in[9];  hd1_bc = (const float*)d_in[10];
        bd0_Wg = (const float*)d_in[11]; bd0_bg = (const float*)d_in[12];
        bd0_Wc = (const float*)d_in[13]; bd0_bc = (const float*)d_in[14];
        bd1_Wg = (const float*)d_in[15]; bd1_bg = (const float*)d_in[16];
        bd1_Wc = (const float*)d_in[17]; bd1_bc = (const float*)d_in[18];
        W_pred = (const float*)d_in[19];
        b_pred = (const float*)d_in[20];
    }

    float* out = (float*)d_out;

    float *XG_h, *XG_b, *out_h, *out_b, *hcat;
    cudaGetSymbolAddress((void**)&XG_h, g_XG_h);
    cudaGetSymbolAddress((void**)&XG_b, g_XG_b);
    cudaGetSymbolAddress((void**)&out_h, g_out_h);
    cudaGetSymbolAddress((void**)&out_b, g_out_b);
    cudaGetSymbolAddress((void**)&hcat, g_hcat);

    const int Mh = BATCH * T_H;
    const int Mb = BATCH * T_B;

    // ---- Layer-0 x-projections (embedding gather fused) ----
    sgemm_kernel<true><<<(Mh / 128) * (512 / 64), 256>>>(
        emb, ids_h, EMB, hd0_Wg, 512, hd0_bg, XG_h, 768, 0,   Mh, 512, EMB);
    sgemm_kernel<true><<<(Mh / 128) * (256 / 64), 256>>>(
        emb, ids_h, EMB, hd0_Wc, 256, hd0_bc, XG_h, 768, 512, Mh, 256, EMB);
    sgemm_kernel<true><<<(Mb / 128) * (512 / 64), 256>>>(
        emb, ids_b, EMB, bd0_Wg, 512, bd0_bg, XG_b, 768, 0,   Mb, 512, EMB);
    sgemm_kernel<true><<<(Mb / 128) * (256 / 64), 256>>>(
        emb, ids_b, EMB, bd0_Wc, 256, bd0_bc, XG_b, 768, 512, Mb, 256, EMB);

    // ---- Layer-0 scan ----
    reset_flags_kernel<<<1, 64>>>();
    {
        ScanArgs body = { XG_b, bd0_Wg + (size_t)EMB * 512, bd0_Wc + (size_t)EMB * 256,
                          ids_b, out_b, nullptr, 0, T_B };
        ScanArgs head = { XG_h, hd0_Wg + (size_t)EMB * 512, hd0_Wc + (size_t)EMB * 256,
                          ids_h, out_h, nullptr, 0, T_H };
        gru_scan_pair_kernel<<<128, 512>>>(body, head);
    }

    // ---- Layer-1 x-projections ----
    sgemm_kernel<false><<<(Mh / 128) * (512 / 64), 256>>>(
        out_h, nullptr, HID, hd1_Wg, 512, hd1_bg, XG_h, 768, 0,   Mh, 512, HID);
    sgemm_kernel<false><<<(Mh / 128) * (256 / 64), 256>>>(
        out_h, nullptr, HID, hd1_Wc, 256, hd1_bc, XG_h, 768, 512, Mh, 256, HID);
    sgemm_kernel<false><<<(Mb / 128) * (512 / 64), 256>>>(
        out_b, nullptr, HID, bd1_Wg, 512, bd1_bg, XG_b, 768, 0,   Mb, 512, HID);
    sgemm_kernel<false><<<(Mb / 128) * (256 / 64), 256>>>(
        out_b, nullptr, HID, bd1_Wc, 256, bd1_bc, XG_b, 768, 512, Mb, 256, HID);

    // ---- Layer-1 scan ----
    reset_flags_kernel<<<1, 64>>>();
    {
        ScanArgs body = { XG_b, bd1_Wg + (size_t)HID * 512, bd1_Wc + (size_t)HID * 256,
                          ids_b, nullptr, hcat, 256, T_B };
        ScanArgs head = { XG_h, hd1_Wg + (size_t)HID * 512, hd1_Wc + (size_t)HID * 256,
                          ids_h, nullptr, hcat, 0, T_H };
        gru_scan_pair_kernel<<<128, 512>>>(body, head);
    }

    // ---- Final projection ----
    final_pred_kernel<<<1, 128>>>(W_pred, b_pred, out);
}

// round 12
// speedup vs baseline: 1.5922x; 1.4272x over previous
#include <cuda_runtime.h>
#include <math.h>

// Problem constants
#define VOCAB 50000
#define EMB   300
#define HID   256
#define BATCH 128
#define T_H   32
#define T_B   512

typedef unsigned long long ULL;

// -------- scratch (static device allocations; no cudaMalloc anywhere) --------
__device__ float g_XG_h[(size_t)BATCH * T_H * 768];   // headline x-projections [B*T, 768]
__device__ float g_XG_b[(size_t)BATCH * T_B * 768];   // body x-projections
__device__ float g_out_h[(size_t)BATCH * T_H * HID];  // headline layer-0 outputs
__device__ float g_out_b[(size_t)BATCH * T_B * HID];  // body layer-0 outputs
__device__ float g_hcat [(size_t)BATCH * 512];        // [h_head | h_body] final states

// ---- packed f32x2 helpers (fp32-exact) ----
__device__ __forceinline__ void fma2(ULL& d, ULL a, ULL b) {
    asm("fma.rn.f32x2 %0, %1, %2, %0;" : "+l"(d) : "l"(a), "l"(b));
}
__device__ __forceinline__ ULL add2(ULL a, ULL b) {
    ULL d; asm("add.rn.f32x2 %0, %1, %2;" : "=l"(d) : "l"(a), "l"(b)); return d;
}
__device__ __forceinline__ ULL dup2(float x) {
    ULL r; asm("mov.b64 %0, {%1, %1};" : "=l"(r) : "f"(x)); return r;
}
__device__ __forceinline__ ULL packf2(float a, float b) {
    ULL r; asm("mov.b64 %0, {%1, %2};" : "=l"(r) : "f"(a), "f"(b)); return r;
}
__device__ __forceinline__ void unpack2(ULL v, float& a, float& b) {
    asm("mov.b64 {%0, %1}, %2;" : "=f"(a), "=f"(b) : "l"(v));
}

// ---- cluster / DSMEM helpers ----
__device__ __forceinline__ void cluster_sync_() {
    asm volatile("barrier.cluster.arrive.aligned;" ::: "memory");
    asm volatile("barrier.cluster.wait.aligned;" ::: "memory");
}
__device__ __forceinline__ unsigned s2u(const void* p) {
    return (unsigned)__cvta_generic_to_shared(p);
}
__device__ __forceinline__ unsigned mapa_sh(unsigned local, unsigned rank) {
    unsigned r;
    asm("mapa.shared::cluster.u32 %0, %1, %2;" : "=r"(r) : "r"(local), "r"(rank));
    return r;
}
__device__ __forceinline__ void st_dsmem_u64(unsigned addr, ULL v) {
    asm volatile("st.shared::cluster.u64 [%0], %1;" :: "r"(addr), "l"(v) : "memory");
}

// ============================================================================
// Generic SGEMM (unchanged): C[M,N] = A[M,K] @ B[K,N] + bias, row-major.
// ============================================================================
template <bool GATHER>
__global__ __launch_bounds__(256)
void sgemm_kernel(const float* __restrict__ A, const int* __restrict__ ids, int lda,
                  const float* __restrict__ Bm, int ldb,
                  const float* __restrict__ bias,
                  float* __restrict__ C, int ldc, int coff,
                  int M, int N, int K)
{
    const int BM = 128, BN = 64, BK = 8;
    __shared__ float As[BK][BM];
    __shared__ float Bs[BK][BN];

    int nbn = N / BN;
    int bm = blockIdx.x / nbn;
    int bn = blockIdx.x % nbn;
    int tid = threadIdx.x;
    int tx = tid & 15;
    int ty = tid >> 4;

    float acc[8][4];
#pragma unroll
    for (int i = 0; i < 8; i++)
#pragma unroll
        for (int j = 0; j < 4; j++) acc[i][j] = 0.0f;

    int ar = tid >> 1;
    int ak = (tid & 1) * 4;
    int arow = bm * BM + ar;
    const float* arow_ptr;
    if (GATHER) arow_ptr = A + (size_t)ids[arow] * lda;
    else        arow_ptr = A + (size_t)arow * lda;

    int bkr = tid >> 5;
    int bc  = (tid & 31) * 2;
    const float* bptr = Bm + (size_t)bn * BN + bc;

    for (int k0 = 0; k0 < K; k0 += BK) {
        float4 av = make_float4(0.f, 0.f, 0.f, 0.f);
        if (k0 + ak < K) av = *(const float4*)(arow_ptr + k0 + ak);
        float2 bv = make_float2(0.f, 0.f);
        if (k0 + bkr < K) bv = *(const float2*)(bptr + (size_t)(k0 + bkr) * ldb);

        __syncthreads();
        As[ak + 0][ar] = av.x; As[ak + 1][ar] = av.y;
        As[ak + 2][ar] = av.z; As[ak + 3][ar] = av.w;
        Bs[bkr][bc] = bv.x; Bs[bkr][bc + 1] = bv.y;
        __syncthreads();

#pragma unroll
        for (int kk = 0; kk < BK; kk++) {
            float4 b4 = *(const float4*)&Bs[kk][tx * 4];
            float4 a0 = *(const float4*)&As[kk][ty * 8];
            float4 a1 = *(const float4*)&As[kk][ty * 8 + 4];
            float arr[8] = {a0.x, a0.y, a0.z, a0.w, a1.x, a1.y, a1.z, a1.w};
            float brr[4] = {b4.x, b4.y, b4.z, b4.w};
#pragma unroll
            for (int i = 0; i < 8; i++)
#pragma unroll
                for (int j = 0; j < 4; j++)
                    acc[i][j] += arr[i] * brr[j];
        }
    }

    float4 bb = *(const float4*)&bias[bn * BN + tx * 4];
    float bbr[4] = {bb.x, bb.y, bb.z, bb.w};
#pragma unroll
    for (int i = 0; i < 8; i++) {
        int row = bm * BM + ty * 8 + i;
        float4 o;
        o.x = acc[i][0] + bbr[0];
        o.y = acc[i][1] + bbr[1];
        o.z = acc[i][2] + bbr[2];
        o.w = acc[i][3] + bbr[3];
        *(float4*)(C + (size_t)row * ldc + coff + bn * BN + tx * 4) = o;
    }
}

// ============================================================================
// GRU scan, round 12: cluster(2) cooperative pairs with DSMEM exchange.
//   cluster = 4 batch rows; role 0 (even CTA): r-gates (cols 0..255) +
//   cand cols [0,128); role 1: u-gates (cols 256..511) + cand [128,256).
//   Per-CTA weight stream halved to 384 KB/step. Per-step vectors move via
//   st.shared::cluster, ordered by 2 cluster barriers per step. h replicated.
// State packed as row-pair f32x2 (rp0 = rows b0,b0+1; rp1 = rows b0+2,b0+3).
// Grid = 128 blocks (64 clusters): [0,64) body, [64,128) head.
// ============================================================================
struct ScanArgs {
    const float* XG;
    const float* Wgh;   // [256,512] k-major h-part of gate weights
    const float* Wch;   // [256,256] k-major h-part of cand weights
    const int*   ids;
    float*       outs;
    float*       hfin;
    int          hoff;
    int          T;
};

__global__ void __cluster_dims__(2, 1, 1) __launch_bounds__(512)
gru_scan_cluster(ScanArgs body, ScanArgs head)
{
    const int bx = blockIdx.x;
    ScanArgs A = (bx < 64) ? body : head;
    const int role = bx & 1;
    const unsigned peer = 1u - (unsigned)role;
    const int pgl = (bx & 63) >> 1;     // group within stream (0..31)
    const int b0  = pgl * 4;            // 4 batch rows
    const int tid = threadIdx.x;
    const int T = A.T;

    __shared__ ULL sh_part[4][256][2];  // matmul partials [ksplit][col][rowpair] 16KB
    __shared__ ULL h_pk [256][2];       // h packed row-pairs                     4KB
    __shared__ ULL rh_pk[256][2];       // r*h packed (written by role 0, both CTAs)
    __shared__ ULL u_pk[2][256][2];     // u packed, double-buffered (role 1)     8KB
    __shared__ ULL c_pk[256][2];        // cand packed (halves from each role)    4KB
    __shared__ int sv[4];

    ((ULL*)h_pk)[tid] = 0ull;           // 512 ULLs
    __syncthreads();

    const int cb  = role << 8;          // gate col base (0 or 256)
    const int cbc = role << 7;          // cand col base (0 or 128)

    // mainloop mappings: 4 k-splits x 128 owners
    const int ks = tid >> 7;            // 0..3 (uniform per warp)
    const int ow = tid & 127;
    const float* wg = A.Wgh + (size_t)(ks * 64) * 512 + cb + ow * 2;   // 2 gate cols
    const float* wc = A.Wch + (size_t)(ks * 64) * 256 + cbc + ow;      // 1 cand col

    // combine mappings
    const int ccol = tid >> 1, crp = tid & 1;          // gate: 256 cols x 2 rowpairs
    const int dcol = (tid & 255) >> 1, drp = tid & 1;  // cand: 128 cols x 2 rowpairs
    // update mapping
    const int ucol = tid & 255, urp = tid >> 8;

    // peer DSMEM base addresses
    const unsigned rh_peer = mapa_sh(s2u(&rh_pk[0][0]), peer);
    const unsigned u_peer  = mapa_sh(s2u(&u_pk[0][0][0]), peer);
    const unsigned c_peer  = mapa_sh(s2u(&c_pk[0][0]), peer);

    cluster_sync_();   // both CTAs alive before any DSMEM traffic

    for (int t = 0; t < T; t++) {
        const int buf = t & 1;

        // ---- prefetch x-parts + validity (long-latency, hidden by gate loop) ----
        float xg0 = A.XG[(size_t)((b0 + 2 * crp)     * T + t) * 768 + cb + ccol];
        float xg1 = A.XG[(size_t)((b0 + 2 * crp + 1) * T + t) * 768 + cb + ccol];
        float xc0 = 0.f, xc1 = 0.f;
        if (tid < 256) {
            xc0 = A.XG[(size_t)((b0 + 2 * drp)     * T + t) * 768 + 512 + cbc + dcol];
            xc1 = A.XG[(size_t)((b0 + 2 * drp + 1) * T + t) * 768 + 512 + cbc + dcol];
        }
        if (tid < 4) sv[tid] = A.ids[(b0 + tid) * T + t];

        // ---- gate mainloop: 2 cols x 2 rowpairs over 64 k ----
        {
            ULL a00 = 0ull, a01 = 0ull, a10 = 0ull, a11 = 0ull;
#pragma unroll 16
            for (int kk = 0; kk < 64; kk++) {
                ULL w2 = *(const ULL*)(wg + (size_t)kk * 512);
                ULL hp0 = h_pk[ks * 64 + kk][0];
                ULL hp1 = h_pk[ks * 64 + kk][1];
                float w0f, w1f; unpack2(w2, w0f, w1f);
                ULL w0 = dup2(w0f), w1 = dup2(w1f);
                fma2(a00, w0, hp0); fma2(a01, w0, hp1);
                fma2(a10, w1, hp0); fma2(a11, w1, hp1);
            }
            sh_part[ks][ow * 2][0]     = a00;
            sh_part[ks][ow * 2][1]     = a01;
            sh_part[ks][ow * 2 + 1][0] = a10;
            sh_part[ks][ow * 2 + 1][1] = a11;
        }
        __syncthreads();

        // ---- gate combine + sigmoid; role 0 -> rh (local+peer), role 1 -> u ----
        {
            ULL s = add2(add2(sh_part[0][ccol][crp], sh_part[1][ccol][crp]),
                         add2(sh_part[2][ccol][crp], sh_part[3][ccol][crp]));
            float s0, s1; unpack2(s, s0, s1);
            float g0 = 1.f / (1.f + expf(-(s0 + xg0)));
            float g1 = 1.f / (1.f + expf(-(s1 + xg1)));
            if (role == 0) {
                float h0, h1; unpack2(h_pk[ccol][crp], h0, h1);
                ULL rh = packf2(g0 * h0, g1 * h1);
                rh_pk[ccol][crp] = rh;
                st_dsmem_u64(rh_peer + (unsigned)(ccol * 2 + crp) * 8u, rh);
            } else {
                ULL u = packf2(g0, g1);
                u_pk[buf][ccol][crp] = u;
                st_dsmem_u64(u_peer + (unsigned)((buf * 256 + ccol) * 2 + crp) * 8u, u);
            }
        }
        cluster_sync_();   // S1: rh visible in both CTAs (u already en route)

        // ---- cand mainloop: 1 col x 2 rowpairs over 64 k ----
        {
            ULL c0a = 0ull, c1a = 0ull;
#pragma unroll 16
            for (int kk = 0; kk < 64; kk++) {
                float w = wc[(size_t)kk * 256];
                ULL wd = dup2(w);
                fma2(c0a, wd, rh_pk[ks * 64 + kk][0]);
                fma2(c1a, wd, rh_pk[ks * 64 + kk][1]);
            }
            sh_part[ks][ow][0] = c0a;
            sh_part[ks][ow][1] = c1a;
        }
        __syncthreads();

        // ---- cand combine + tanh (tid < 256); own half local + peer ----
        if (tid < 256) {
            ULL s = add2(add2(sh_part[0][dcol][drp], sh_part[1][dcol][drp]),
                         add2(sh_part[2][dcol][drp], sh_part[3][dcol][drp]));
            float s0, s1; unpack2(s, s0, s1);
            ULL c = packf2(tanhf(s0 + xc0), tanhf(s1 + xc1));
            int gc = cbc + dcol;
            c_pk[gc][drp] = c;
            st_dsmem_u64(c_peer + (unsigned)(gc * 2 + drp) * 8u, c);
        }
        cluster_sync_();   // S2: c complete in both CTAs

        // ---- update (replicated in both CTAs; bit-identical inputs) ----
        {
            float u0, u1, c0, c1, h0, h1;
            unpack2(u_pk[buf][ucol][urp], u0, u1);
            unpack2(c_pk[ucol][urp],      c0, c1);
            unpack2(h_pk[ucol][urp],      h0, h1);
            float hn0 = u0 * h0 + (1.f - u0) * c0;
            float hn1 = u1 * h1 + (1.f - u1) * c1;
            bool v0 = sv[2 * urp] != 0, v1 = sv[2 * urp + 1] != 0;
            h_pk[ucol][urp] = packf2(v0 ? hn0 : h0, v1 ? hn1 : h1);
            if (A.outs && (ucol >> 7) == role) {
                A.outs[(size_t)((b0 + 2 * urp)     * T + t) * 256 + ucol] = v0 ? hn0 : 0.f;
                A.outs[(size_t)((b0 + 2 * urp + 1) * T + t) * 256 + ucol] = v1 ? hn1 : 0.f;
            }
        }
        __syncthreads();   // h_pk ready for next gate mainloop
    }

    // ---- final hidden state (own column half) ----
    if (A.hfin && (ucol >> 7) == role) {
        float k0, k1; unpack2(h_pk[ucol][urp], k0, k1);
        A.hfin[(size_t)(b0 + 2 * urp)     * 512 + A.hoff + ucol] = k0;
        A.hfin[(size_t)(b0 + 2 * urp + 1) * 512 + A.hoff + ucol] = k1;
    }
    cluster_sync_();   // no CTA exits while peer may still DSMEM-target it
}

// ============================================================================
// Final projection: out[128,4] = [h_head | h_body] @ W_pred + b_pred
// ============================================================================
__global__ void final_pred_kernel(const float* __restrict__ Wp,
                                  const float* __restrict__ bp,
                                  float* __restrict__ out)
{
    int b = threadIdx.x;
    float a0 = bp[0], a1 = bp[1], a2 = bp[2], a3 = bp[3];
    const float* h = g_hcat + (size_t)b * 512;
#pragma unroll 8
    for (int j = 0; j < 512; j++) {
        float hv = h[j];
        float4 w = *(const float4*)(Wp + j * 4);
        a0 += hv * w.x; a1 += hv * w.y; a2 += hv * w.z; a3 += hv * w.w;
    }
    *(float4*)(out + b * 4) = make_float4(a0, a1, a2, a3);
}

// ============================================================================
// Launch
// ============================================================================
extern "C" void kernel_launch(void* const* d_in, const int* in_sizes, int n_in,
                              void* d_out, int out_size)
{
    (void)n_in; (void)out_size;

    const int*   ids_h  = (const int*)d_in[0];
    const int*   ids_b  = (const int*)d_in[1];
    const float* emb    = (const float*)d_in[2];

    const float *hd0_Wg, *hd0_bg, *hd0_Wc, *hd0_bc;
    const float *hd1_Wg, *hd1_bg, *hd1_Wc, *hd1_bc;
    const float *bd0_Wg, *bd0_bg, *bd0_Wc, *bd0_bc;
    const float *bd1_Wg, *bd1_bg, *bd1_Wc, *bd1_bc;
    const float *W_pred, *b_pred;

    if (in_sizes[3] == (2 * HID) * 4 && in_sizes[4] == 4) {
        W_pred = (const float*)d_in[3];
        b_pred = (const float*)d_in[4];
        hd0_Wg = (const float*)d_in[5];  hd0_bg = (const float*)d_in[6];
        hd0_Wc = (const float*)d_in[7];  hd0_bc = (const float*)d_in[8];
        hd1_Wg = (const float*)d_in[9];  hd1_bg = (const float*)d_in[10];
        hd1_Wc = (const float*)d_in[11]; hd1_bc = (const float*)d_in[12];
        bd0_Wg = (const float*)d_in[13]; bd0_bg = (const float*)d_in[14];
        bd0_Wc = (const float*)d_in[15]; bd0_bc = (const float*)d_in[16];
        bd1_Wg = (const float*)d_in[17]; bd1_bg = (const float*)d_in[18];
        bd1_Wc = (const float*)d_in[19]; bd1_bc = (const float*)d_in[20];
    } else {
        hd0_Wg = (const float*)d_in[3];  hd0_bg = (const float*)d_in[4];
        hd0_Wc = (const float*)d_in[5];  hd0_bc = (const float*)d_in[6];
        hd1_Wg = (const float*)d_in[7];  hd1_bg = (const float*)d_in[8];
        hd1_Wc = (const float*)d_in[9];  hd1_bc = (const float*)d_in[10];
        bd0_Wg = (const float*)d_in[11]; bd0_bg = (const float*)d_in[12];
        bd0_Wc = (const float*)d_in[13]; bd0_bc = (const float*)d_in[14];
        bd1_Wg = (const float*)d_in[15]; bd1_bg = (const float*)d_in[16];
        bd1_Wc = (const float*)d_in[17]; bd1_bc = (const float*)d_in[18];
        W_pred = (const float*)d_in[19];
        b_pred = (const float*)d_in[20];
    }

    float* out = (float*)d_out;

    float *XG_h, *XG_b, *out_h, *out_b, *hcat;
    cudaGetSymbolAddress((void**)&XG_h, g_XG_h);
    cudaGetSymbolAddress((void**)&XG_b, g_XG_b);
    cudaGetSymbolAddress((void**)&out_h, g_out_h);
    cudaGetSymbolAddress((void**)&out_b, g_out_b);
    cudaGetSymbolAddress((void**)&hcat, g_hcat);

    const int Mh = BATCH * T_H;
    const int Mb = BATCH * T_B;

    // ---- Layer-0 x-projections (embedding gather fused) ----
    sgemm_kernel<true><<<(Mh / 128) * (512 / 64), 256>>>(
        emb, ids_h, EMB, hd0_Wg, 512, hd0_bg, XG_h, 768, 0,   Mh, 512, EMB);
    sgemm_kernel<true><<<(Mh / 128) * (256 / 64), 256>>>(
        emb, ids_h, EMB, hd0_Wc, 256, hd0_bc, XG_h, 768, 512, Mh, 256, EMB);
    sgemm_kernel<true><<<(Mb / 128) * (512 / 64), 256>>>(
        emb, ids_b, EMB, bd0_Wg, 512, bd0_bg, XG_b, 768, 0,   Mb, 512, EMB);
    sgemm_kernel<true><<<(Mb / 128) * (256 / 64), 256>>>(
        emb, ids_b, EMB, bd0_Wc, 256, bd0_bc, XG_b, 768, 512, Mb, 256, EMB);

    // ---- Layer-0 scan ----
    {
        ScanArgs body = { XG_b, bd0_Wg + (size_t)EMB * 512, bd0_Wc + (size_t)EMB * 256,
                          ids_b, out_b, nullptr, 0, T_B };
        ScanArgs head = { XG_h, hd0_Wg + (size_t)EMB * 512, hd0_Wc + (size_t)EMB * 256,
                          ids_h, out_h, nullptr, 0, T_H };
        gru_scan_cluster<<<128, 512>>>(body, head);
    }

    // ---- Layer-1 x-projections ----
    sgemm_kernel<false><<<(Mh / 128) * (512 / 64), 256>>>(
        out_h, nullptr, HID, hd1_Wg, 512, hd1_bg, XG_h, 768, 0,   Mh, 512, HID);
    sgemm_kernel<false><<<(Mh / 128) * (256 / 64), 256>>>(
        out_h, nullptr, HID, hd1_Wc, 256, hd1_bc, XG_h, 768, 512, Mh, 256, HID);
    sgemm_kernel<false><<<(Mb / 128) * (512 / 64), 256>>>(
        out_b, nullptr, HID, bd1_Wg, 512, bd1_bg, XG_b, 768, 0,   Mb, 512, HID);
    sgemm_kernel<false><<<(Mb / 128) * (256 / 64), 256>>>(
        out_b, nullptr, HID, bd1_Wc, 256, bd1_bc, XG_b, 768, 512, Mb, 256, HID);

    // ---- Layer-1 scan ----
    {
        ScanArgs body = { XG_b, bd1_Wg + (size_t)HID * 512, bd1_Wc + (size_t)HID * 256,
                          ids_b, nullptr, hcat, 256, T_B };
        ScanArgs head = { XG_h, hd1_Wg + (size_t)HID * 512, hd1_Wc + (size_t)HID * 256,
                          ids_h, nullptr, hcat, 0, T_H };
        gru_scan_cluster<<<128, 512>>>(body, head);
    }

    // ---- Final projection ----
    final_pred_kernel<<<1, 128>>>(W_pred, b_pred, out);
}